// round 16
// baseline (speedup 1.0000x reference)
#include <cuda_runtime.h>
#include <cuda_bf16.h>
#include <cuda_fp16.h>
#include <cstdint>

#define NN   1024
#define NN2  (NN * NN)
#define BD   64
#define NB   128
#define ROWB 144         // 128B k-data (BK=64) + 16B pad

// ============================================================================
// Device global scratch (allocation-free rule).  Single-fp16 operator tree:
//   A = C0 + C1*Q + (C2 + C3*Q)*Q^2,  Cj = W2j + W2j+1*S,  Q = S^2.
// ============================================================================
__device__ __align__(16) __half g_Ss[NN2];     // S   row-major fp16
__device__ __align__(16) __half g_St[NN2];     // S^T row-major fp16 (K-major B)
__device__ __align__(16) __half g_W1[NN2], g_W3[NN2], g_W5[NN2], g_W7[NN2];
__device__ __align__(16) __half g_Q[NN2],  g_Qt[NN2];
__device__ __align__(16) __half g_C0[NN2], g_C1[NN2], g_C2[NN2], g_C3[NN2];
__device__ __align__(16) __half g_B0[NN2], g_B1[NN2], g_Q2t[NN2];
__device__ __align__(16) __half g_A[NN2];
__device__ __align__(16) __half g_Xh[(size_t)NB * BD * NN];    // X^T fp16

// ============================================================================
// PTX helpers (baseline sm_80-class, legal under compute_103)
// ============================================================================
__device__ __forceinline__ uint32_t smem_to_u32(const void* p) {
    uint32_t a;
    asm("{ .reg .u64 t; cvta.to.shared.u64 t, %1; cvt.u32.u64 %0, t; }"
        : "=r"(a) : "l"(p));
    return a;
}
__device__ __forceinline__ void cp16(uint32_t s, const void* g) {
    asm volatile("cp.async.cg.shared.global [%0], [%1], 16;" :: "r"(s), "l"(g));
}
#define CP_COMMIT() asm volatile("cp.async.commit_group;" ::: "memory")
#define CP_WAIT(n)  asm volatile("cp.async.wait_group %0;" :: "n"(n) : "memory")

__device__ __forceinline__ void ldsm4(uint32_t& r0, uint32_t& r1,
                                      uint32_t& r2, uint32_t& r3, uint32_t a) {
    asm volatile("ldmatrix.sync.aligned.m8n8.x4.shared.b16 {%0,%1,%2,%3}, [%4];"
                 : "=r"(r0), "=r"(r1), "=r"(r2), "=r"(r3) : "r"(a));
}
__device__ __forceinline__ void mma_f16(float* c, const uint32_t* a,
                                        uint32_t b0, uint32_t b1) {
    asm volatile(
        "mma.sync.aligned.m16n8k16.row.col.f32.f16.f16.f32 "
        "{%0,%1,%2,%3}, {%4,%5,%6,%7}, {%8,%9}, {%0,%1,%2,%3};"
        : "+f"(c[0]), "+f"(c[1]), "+f"(c[2]), "+f"(c[3])
        : "r"(a[0]), "r"(a[1]), "r"(a[2]), "r"(a[3]), "r"(b0), "r"(b1));
}

// ============================================================================
// Converts
// ============================================================================
// St[n][k] = fp16(S[k][n])
__global__ __launch_bounds__(256) void convert_St(const float* __restrict__ S) {
    __shared__ float tile[64][65];
    int k0 = blockIdx.x * 64, n0 = blockIdx.y * 64;
    for (int idx = threadIdx.x; idx < 64 * 64; idx += 256) {
        int r = idx >> 6, c = idx & 63;
        tile[r][c] = S[(size_t)(k0 + r) * NN + n0 + c];
    }
    __syncthreads();
    for (int idx = threadIdx.x; idx < 64 * 64; idx += 256) {
        int r = idx >> 6, c = idx & 63;
        g_St[(size_t)(n0 + r) * NN + k0 + c] = __float2half(tile[c][r]);
    }
}
// Elementwise fp16 converts: y=0 -> Ss; y=1..4 -> W1, W3, W5, W7
__global__ __launch_bounds__(256)
void convert_elem(const float* __restrict__ S, const float* __restrict__ weight) {
    size_t i = ((size_t)blockIdx.x * 256 + threadIdx.x) * 2;
    int y = blockIdx.y;
    const float* src;
    __half* dst;
    if (y == 0)      { src = S;                        dst = g_Ss; }
    else if (y == 1) { src = weight + (size_t)1 * NN2; dst = g_W1; }
    else if (y == 2) { src = weight + (size_t)3 * NN2; dst = g_W3; }
    else if (y == 3) { src = weight + (size_t)5 * NN2; dst = g_W5; }
    else             { src = weight + (size_t)7 * NN2; dst = g_W7; }
    float2 v = *(const float2*)&src[i];
    *(__half2*)(dst + i) = __halves2half2(__float2half(v.x), __float2half(v.y));
}
// Xh[b][d][k] = fp16(X[b][k][d])
__global__ __launch_bounds__(256) void convert_X(const float* __restrict__ X) {
    __shared__ float tile[64][65];
    int k0 = blockIdx.x * 64, b = blockIdx.y;
    for (int idx = threadIdx.x; idx < 64 * 64; idx += 256) {
        int r = idx >> 6, c = idx & 63;
        tile[r][c] = X[((size_t)b * NN + k0 + r) * BD + c];
    }
    __syncthreads();
    for (int idx = threadIdx.x; idx < 64 * 64; idx += 256) {
        int r = idx >> 6, c = idx & 63;
        g_Xh[((size_t)b * BD + r) * NN + k0 + c] = __float2half(tile[c][r]);
    }
}

// ============================================================================
// Fragment / MMA macros (proven 256-thr 128x128 core)
// ============================================================================
#define LDS_A(a, k16, sA)                                                     \
    _Pragma("unroll")                                                         \
    for (int _mt = 0; _mt < 4; ++_mt)                                         \
        ldsm4((a)[_mt][0], (a)[_mt][1], (a)[_mt][2], (a)[_mt][3],             \
              (sA) + (uint32_t)(wm + _mt * 16 + (lane & 15)) * ROWB           \
                   + (uint32_t)((k16) * 2 + (lane >> 4)) * 16)

#define LDS_B(b, k16, sB)                                                     \
    _Pragma("unroll")                                                         \
    for (int _p = 0; _p < 2; ++_p)                                            \
        ldsm4((b)[_p][0], (b)[_p][1], (b)[_p][2], (b)[_p][3],                 \
              (sB) + (uint32_t)(wn + _p * 16 + ((lane >> 4) << 3) + (lane & 7)) * ROWB \
                   + (uint32_t)((k16) * 2 + ((lane >> 3) & 1)) * 16)

#define MMA_ALL(acc, a, b)                                                    \
    _Pragma("unroll")                                                         \
    for (int _mt = 0; _mt < 4; ++_mt)                                         \
        _Pragma("unroll")                                                     \
        for (int _nt = 0; _nt < 4; ++_nt)                                     \
            mma_f16((acc)[_mt][_nt], (a)[_mt],                                \
                    (b)[_nt >> 1][(_nt & 1) * 2], (b)[_nt >> 1][(_nt & 1) * 2 + 1])

#define STG_BYTES (256 * ROWB)
#define OP_SMEM   (3 * STG_BYTES)

// ============================================================================
// gemm_op: C = A @ B^T (+ add), K = 1024, tile 128x128, 16 stages, 3-ring.
// Job table by (level, z):
//  L1: z0 Q=Ss*St, z1 Qt=St*Ss, z2..5 Cj=W(2j+1)*St + W2j(fp32)
//  L2: z0 B0=C1*Qt+C0, z1 B1=C3*Qt+C2, z2 Q2t=Qt*Q
//  L3: z0 A=B1*Q2t+B0
// ============================================================================
__global__ __launch_bounds__(256, 2)
void gemm_op(int level, const float* __restrict__ weight) {
    extern __shared__ __align__(16) char smem[];
    const int tid  = threadIdx.x;
    const int lane = tid & 31, w = tid >> 5;
    const int wm   = (w >> 2) * 64;
    const int wn   = (w & 3) * 32;
    const int row0 = blockIdx.y * 128;
    const int col0 = blockIdx.x * 128;
    const int z    = blockIdx.z;
    const uint32_t sbase = smem_to_u32(smem);

    // ---- job resolution ----
    const __half *Ap, *Bp;
    const __half *adH = nullptr;
    const float  *adF = nullptr;
    __half *Oh;
    if (level == 1) {
        if (z == 0)      { Ap = g_Ss; Bp = g_St; Oh = g_Q; }
        else if (z == 1) { Ap = g_St; Bp = g_Ss; Oh = g_Qt; }
        else {
            int j = z - 2;
            Bp = g_St;
            if (j == 0)      { Ap = g_W1; Oh = g_C0; }
            else if (j == 1) { Ap = g_W3; Oh = g_C1; }
            else if (j == 2) { Ap = g_W5; Oh = g_C2; }
            else             { Ap = g_W7; Oh = g_C3; }
            adF = weight + (size_t)(2 * j) * NN2;
        }
    } else if (level == 2) {
        if (z == 0)      { Ap = g_C1; Bp = g_Qt; adH = g_C0; Oh = g_B0; }
        else if (z == 1) { Ap = g_C3; Bp = g_Qt; adH = g_C2; Oh = g_B1; }
        else             { Ap = g_Qt; Bp = g_Q;  Oh = g_Q2t; }
    } else {
        Ap = g_B1; Bp = g_Q2t; adH = g_B0; Oh = g_A;
    }

    auto issue = [&](int s, int slot) {
        const int k = s * 64;
        const uint32_t base = sbase + slot * STG_BYTES;
        #pragma unroll
        for (int i = 0; i < 8; ++i) {
            int idx = tid + i * 256;           // 0..2047
            int r = idx >> 3, c = idx & 7;
            const __half* src = (r < 128)
                ? Ap + (size_t)(row0 + r) * NN + k + c * 8
                : Bp + (size_t)(col0 + r - 128) * NN + k + c * 8;
            cp16(base + r * ROWB + c * 16, src);
        }
        CP_COMMIT();
    };

    float acc[4][4][4] = {};
    issue(0, 0); issue(1, 1);

    for (int s = 0; s < 16; ++s) {
        CP_WAIT(1);
        __syncthreads();
        const uint32_t sA = sbase + (s % 3) * STG_BYTES;
        const uint32_t sB = sA + 128 * ROWB;

        uint32_t a[4][4], b[2][4];
        LDS_A(a, 0, sA); LDS_B(b, 0, sB);
        if (s + 2 < 16) issue(s + 2, (s + 2) % 3); else CP_COMMIT();
        MMA_ALL(acc, a, b);
        #pragma unroll
        for (int k16 = 1; k16 < 4; ++k16) {
            LDS_A(a, k16, sA); LDS_B(b, k16, sB);
            MMA_ALL(acc, a, b);
        }
    }

    // ---- epilogue: + add, convert fp16, store ----
    const int g  = lane >> 2;
    const int i2 = (lane & 3) * 2;
    #pragma unroll
    for (int mt = 0; mt < 4; ++mt)
        #pragma unroll
        for (int nt = 0; nt < 4; ++nt) {
            const int m0 = row0 + wm + mt * 16 + g;
            const int n  = col0 + wn + nt * 8 + i2;
            float a00 = 0.f, a01 = 0.f, a10 = 0.f, a11 = 0.f;
            if (adF) {
                float2 w0 = *(const float2*)(adF + (size_t)m0 * NN + n);
                float2 w1 = *(const float2*)(adF + (size_t)(m0 + 8) * NN + n);
                a00 = w0.x; a01 = w0.y; a10 = w1.x; a11 = w1.y;
            } else if (adH) {
                __half2 h0 = *(const __half2*)(adH + (size_t)m0 * NN + n);
                __half2 h1 = *(const __half2*)(adH + (size_t)(m0 + 8) * NN + n);
                a00 = __half2float(h0.x); a01 = __half2float(h0.y);
                a10 = __half2float(h1.x); a11 = __half2float(h1.y);
            }
            *(__half2*)(Oh + (size_t)m0 * NN + n) =
                __halves2half2(__float2half(acc[mt][nt][0] + a00),
                               __float2half(acc[mt][nt][1] + a01));
            *(__half2*)(Oh + (size_t)(m0 + 8) * NN + n) =
                __halves2half2(__float2half(acc[mt][nt][2] + a10),
                               __float2half(acc[mt][nt][3] + a11));
        }
}

// ============================================================================
// gemm_final: out = A @ Xh  — fp16, K = 1024, fp32 output scatter.
// grid (64, 8) = 512 CTAs, 256 threads.  [R13-proven]
// ============================================================================
__global__ __launch_bounds__(256, 2)
void gemm_final(float* __restrict__ outp) {
    extern __shared__ __align__(16) char smem[];
    const int tid  = threadIdx.x;
    const int lane = tid & 31, w = tid >> 5;
    const int wm   = (w >> 2) * 64;
    const int wn   = (w & 3) * 32;
    const int row0 = blockIdx.y * 128;
    const int col0 = blockIdx.x * 128;     // global column in [0, 8192)
    const uint32_t sbase = smem_to_u32(smem);

    auto issue = [&](int s, int slot) {
        const int k = s * 64;
        const uint32_t base = sbase + slot * STG_BYTES;
        #pragma unroll
        for (int i = 0; i < 8; ++i) {
            int idx = tid + i * 256;
            int r = idx >> 3, c = idx & 7;
            const __half* src = (r < 128)
                ? g_A  + (size_t)(row0 + r) * NN + k + c * 8
                : g_Xh + (size_t)(col0 + r - 128) * NN + k + c * 8;
            cp16(base + r * ROWB + c * 16, src);
        }
        CP_COMMIT();
    };

    float acc[4][4][4] = {};
    issue(0, 0); issue(1, 1);

    for (int s = 0; s < 16; ++s) {
        CP_WAIT(1);
        __syncthreads();
        const uint32_t sA = sbase + (s % 3) * STG_BYTES;
        const uint32_t sB = sA + 128 * ROWB;

        uint32_t a[4][4], b[2][4];
        LDS_A(a, 0, sA); LDS_B(b, 0, sB);
        if (s + 2 < 16) issue(s + 2, (s + 2) % 3); else CP_COMMIT();
        MMA_ALL(acc, a, b);
        #pragma unroll
        for (int k16 = 1; k16 < 4; ++k16) {
            LDS_A(a, k16, sA); LDS_B(b, k16, sB);
            MMA_ALL(acc, a, b);
        }
    }

    const int g  = lane >> 2;
    const int i2 = (lane & 3) * 2;
    #pragma unroll
    for (int mt = 0; mt < 4; ++mt)
        #pragma unroll
        for (int nt = 0; nt < 4; ++nt) {
            const int m0    = row0 + wm + mt * 16 + g;
            const int ncolg = col0 + wn + nt * 8 + i2;
            const int batch = ncolg >> 6;
            const int d     = ncolg & 63;
            float* o0 = outp + ((size_t)batch * NN + m0) * BD + d;
            float* o1 = outp + ((size_t)batch * NN + m0 + 8) * BD + d;
            *(float2*)o0 = make_float2(acc[mt][nt][0], acc[mt][nt][1]);
            *(float2*)o1 = make_float2(acc[mt][nt][2], acc[mt][nt][3]);
        }
}

// ============================================================================
// Host orchestration (log-depth tree, single-fp16):
//   L1: Q, Qt, C0..C3   L2: B0, B1, Q2t   L3: A   final: out = A @ X
// ============================================================================
extern "C" void kernel_launch(void* const* d_in, const int* in_sizes, int n_in,
                              void* d_out, int out_size) {
    const float* nodes  = (const float*)d_in[0];   // [128, 1024, 64]
    const float* weight = (const float*)d_in[1];   // [8, 1024, 1024]
    const float* S      = (const float*)d_in[2];   // [1024, 1024]
    float* out = (float*)d_out;                    // [128, 1024, 64]

    cudaFuncSetAttribute(gemm_op,    cudaFuncAttributeMaxDynamicSharedMemorySize, OP_SMEM);
    cudaFuncSetAttribute(gemm_final, cudaFuncAttributeMaxDynamicSharedMemorySize, OP_SMEM);

    convert_St  <<<dim3(16, 16), 256>>>(S);
    convert_elem<<<dim3(NN2 / 512, 5), 256>>>(S, weight);
    convert_X   <<<dim3(16, NB), 256>>>(nodes);

    gemm_op<<<dim3(8, 8, 6), 256, OP_SMEM>>>(1, weight);  // Q, Qt, C0..C3
    gemm_op<<<dim3(8, 8, 3), 256, OP_SMEM>>>(2, weight);  // B0, B1, Q2t
    gemm_op<<<dim3(8, 8, 1), 256, OP_SMEM>>>(3, weight);  // A
    gemm_final<<<dim3(64, 8), 256, OP_SMEM>>>(out);       // out = A @ X
}

// round 17
// speedup vs baseline: 1.1311x; 1.1311x over previous
#include <cuda_runtime.h>
#include <cuda_bf16.h>
#include <cuda_fp16.h>
#include <cstdint>

#define NN   1024
#define NN2  (NN * NN)
#define BD   64
#define NB   128
#define ROWB 144         // 128B k-data (BK=64) + 16B pad

// ============================================================================
// Device global scratch (allocation-free rule).  Single-fp16 pipeline:
//   T, S, X all fp16; fp32 accumulation everywhere.
// ============================================================================
__device__ __align__(16) __half g_Sh[NN2];                         // S^T, fp16
__device__ __align__(16) __half g_Ta_h[NN2];
__device__ __align__(16) __half g_Tb_h[NN2];
__device__ __align__(16) __half g_Xh[(size_t)NB * BD * NN];        // X^T, fp16

// ============================================================================
// PTX helpers (baseline sm_80-class, legal under compute_103)
// ============================================================================
__device__ __forceinline__ uint32_t smem_to_u32(const void* p) {
    uint32_t a;
    asm("{ .reg .u64 t; cvta.to.shared.u64 t, %1; cvt.u32.u64 %0, t; }"
        : "=r"(a) : "l"(p));
    return a;
}
__device__ __forceinline__ void cp16(uint32_t s, const void* g) {
    asm volatile("cp.async.cg.shared.global [%0], [%1], 16;" :: "r"(s), "l"(g));
}
#define CP_COMMIT() asm volatile("cp.async.commit_group;" ::: "memory")
#define CP_WAIT(n)  asm volatile("cp.async.wait_group %0;" :: "n"(n) : "memory")

__device__ __forceinline__ void ldsm4(uint32_t& r0, uint32_t& r1,
                                      uint32_t& r2, uint32_t& r3, uint32_t a) {
    asm volatile("ldmatrix.sync.aligned.m8n8.x4.shared.b16 {%0,%1,%2,%3}, [%4];"
                 : "=r"(r0), "=r"(r1), "=r"(r2), "=r"(r3) : "r"(a));
}
__device__ __forceinline__ void mma_f16(float* c, const uint32_t* a,
                                        uint32_t b0, uint32_t b1) {
    asm volatile(
        "mma.sync.aligned.m16n8k16.row.col.f32.f16.f16.f32 "
        "{%0,%1,%2,%3}, {%4,%5,%6,%7}, {%8,%9}, {%0,%1,%2,%3};"
        : "+f"(c[0]), "+f"(c[1]), "+f"(c[2]), "+f"(c[3])
        : "r"(a[0]), "r"(a[1]), "r"(a[2]), "r"(a[3]), "r"(b0), "r"(b1));
}

// ============================================================================
// Converts
// ============================================================================
// Sh[n][k] = fp16(S[k][n])
__global__ __launch_bounds__(256) void convert_St(const float* __restrict__ S) {
    __shared__ float tile[64][65];
    int k0 = blockIdx.x * 64, n0 = blockIdx.y * 64;
    for (int idx = threadIdx.x; idx < 64 * 64; idx += 256) {
        int r = idx >> 6, c = idx & 63;
        tile[r][c] = S[(size_t)(k0 + r) * NN + n0 + c];
    }
    __syncthreads();
    for (int idx = threadIdx.x; idx < 64 * 64; idx += 256) {
        int r = idx >> 6, c = idx & 63;
        g_Sh[(size_t)(n0 + r) * NN + k0 + c] = __float2half(tile[c][r]);
    }
}
// Xh[b][d][k] = fp16(X[b][k][d])
__global__ __launch_bounds__(256) void convert_X(const float* __restrict__ X) {
    __shared__ float tile[64][65];
    int k0 = blockIdx.x * 64, b = blockIdx.y;
    for (int idx = threadIdx.x; idx < 64 * 64; idx += 256) {
        int r = idx >> 6, c = idx & 63;
        tile[r][c] = X[((size_t)b * NN + k0 + r) * BD + c];
    }
    __syncthreads();
    for (int idx = threadIdx.x; idx < 64 * 64; idx += 256) {
        int r = idx >> 6, c = idx & 63;
        g_Xh[((size_t)b * BD + r) * NN + k0 + c] = __float2half(tile[c][r]);
    }
}
// Ta = fp16(W7)
__global__ __launch_bounds__(256) void convert_init(const float* __restrict__ W7) {
    size_t i = ((size_t)blockIdx.x * 256 + threadIdx.x) * 2;
    float2 v = *(const float2*)&W7[i];
    *(__half2*)(g_Ta_h + i) = __halves2half2(__float2half(v.x), __float2half(v.y));
}

// ============================================================================
// Fragment / MMA macros
// ============================================================================
#define LDS_Am(a, M, k16, sA)                                                 \
    _Pragma("unroll")                                                         \
    for (int _mt = 0; _mt < (M); ++_mt)                                       \
        ldsm4((a)[_mt][0], (a)[_mt][1], (a)[_mt][2], (a)[_mt][3],             \
              (sA) + (uint32_t)(wm + _mt * 16 + (lane & 15)) * ROWB           \
                   + (uint32_t)((k16) * 2 + (lane >> 4)) * 16)

#define LDS_B(b, k16, sB)                                                     \
    _Pragma("unroll")                                                         \
    for (int _p = 0; _p < 2; ++_p)                                            \
        ldsm4((b)[_p][0], (b)[_p][1], (b)[_p][2], (b)[_p][3],                 \
              (sB) + (uint32_t)(wn + _p * 16 + ((lane >> 4) << 3) + (lane & 7)) * ROWB \
                   + (uint32_t)((k16) * 2 + ((lane >> 3) & 1)) * 16)

#define MMA_Mx4(acc, a, b, M)                                                 \
    _Pragma("unroll")                                                         \
    for (int _mt = 0; _mt < (M); ++_mt)                                       \
        _Pragma("unroll")                                                     \
        for (int _nt = 0; _nt < 4; ++_nt)                                     \
            mma_f16((acc)[_mt][_nt], (a)[_mt],                                \
                    (b)[_nt >> 1][(_nt & 1) * 2], (b)[_nt >> 1][(_nt & 1) * 2 + 1])

// ============================================================================
// gemm_step: T_next(64x64 tile) = fp16( T @ Sh + Wk )  over K = 1024.
// grid (16, 16) = 256 CTAs, 128 thr (warps 2Mx2N, warp tile 32x32).
// 16 stages of BK=64; **6-stage ring, 5 stages in flight** to bury L2 latency.
// Stage = 128 rows x 144B = 18432 B; smem = 110592 B (2 CTAs/SM).
// ============================================================================
#define ST_STG   (128 * ROWB)
#define ST_RING  6
#define ST_SMEM  (ST_RING * ST_STG)

__global__ __launch_bounds__(128, 2)
void gemm_step(int inSel, const float* __restrict__ Wk) {
    extern __shared__ __align__(16) char smem[];
    const int tid  = threadIdx.x;
    const int lane = tid & 31, w = tid >> 5;
    const int wm   = (w >> 1) * 32;       // 0, 32
    const int wn   = (w & 1) * 32;        // 0, 32
    const int row0 = blockIdx.y * 64;
    const int col0 = blockIdx.x * 64;
    const uint32_t sbase = smem_to_u32(smem);

    const __half* Ap = inSel ? g_Tb_h : g_Ta_h;
    __half*       Oh = inSel ? g_Ta_h : g_Tb_h;

    auto issue = [&](int s, int slot) {
        const int k = s * 64;
        const uint32_t base = sbase + slot * ST_STG;
        #pragma unroll
        for (int i = 0; i < 8; ++i) {
            int idx = tid + i * 128;           // 0..1023
            int r = idx >> 3, c = idx & 7;
            const __half* src = (r < 64)
                ? Ap   + (size_t)(row0 + r) * NN + k + c * 8
                : g_Sh + (size_t)(col0 + r - 64) * NN + k + c * 8;
            cp16(base + r * ROWB + c * 16, src);
        }
        CP_COMMIT();
    };

    float acc[2][4][4] = {};
    issue(0, 0); issue(1, 1); issue(2, 2); issue(3, 3); issue(4, 4);

    for (int s = 0; s < 16; ++s) {
        CP_WAIT(4);
        __syncthreads();
        const uint32_t sA = sbase + (s % ST_RING) * ST_STG;
        const uint32_t sB = sA + 64 * ROWB;

        uint32_t a[2][4], b[2][4];
        LDS_Am(a, 2, 0, sA); LDS_B(b, 0, sB);
        if (s + 5 < 16) issue(s + 5, (s + 5) % ST_RING); else CP_COMMIT();
        MMA_Mx4(acc, a, b, 2);
        #pragma unroll
        for (int k16 = 1; k16 < 4; ++k16) {
            LDS_Am(a, 2, k16, sA); LDS_B(b, k16, sB);
            MMA_Mx4(acc, a, b, 2);
        }
    }

    // epilogue: + Wk (fp32), convert fp16, store T_next
    const int g  = lane >> 2;
    const int i2 = (lane & 3) * 2;
    #pragma unroll
    for (int mt = 0; mt < 2; ++mt)
        #pragma unroll
        for (int nt = 0; nt < 4; ++nt) {
            const int m0 = row0 + wm + mt * 16 + g;
            const int n  = col0 + wn + nt * 8 + i2;
            float2 w0 = *(const float2*)(Wk + (size_t)m0 * NN + n);
            float2 w1 = *(const float2*)(Wk + (size_t)(m0 + 8) * NN + n);
            *(__half2*)(Oh + (size_t)m0 * NN + n) =
                __halves2half2(__float2half(acc[mt][nt][0] + w0.x),
                               __float2half(acc[mt][nt][1] + w0.y));
            *(__half2*)(Oh + (size_t)(m0 + 8) * NN + n) =
                __halves2half2(__float2half(acc[mt][nt][2] + w1.x),
                               __float2half(acc[mt][nt][3] + w1.y));
        }
}

// ============================================================================
// gemm_final: out = Th @ Xh  — fp16, K = 1024 (16 stages), 3-stage ring.
// grid (64, 8) = 512 CTAs, 256 thr (warps 2Mx4N, warp tile 64x32).
// [R13/R15-proven config — unchanged]
// ============================================================================
#define F_STG   (256 * ROWB)
#define F_SMEM  (3 * F_STG)

__global__ __launch_bounds__(256, 2)
void gemm_final(float* __restrict__ outp) {
    extern __shared__ __align__(16) char smem[];
    const int tid  = threadIdx.x;
    const int lane = tid & 31, w = tid >> 5;
    const int wm   = (w >> 2) * 64;
    const int wn   = (w & 3) * 32;
    const int row0 = blockIdx.y * 128;
    const int col0 = blockIdx.x * 128;     // global column in [0, 8192)
    const uint32_t sbase = smem_to_u32(smem);

    auto issue = [&](int s, int slot) {
        const int k = s * 64;              // 0..1023
        const uint32_t base = sbase + slot * F_STG;
        #pragma unroll
        for (int i = 0; i < 8; ++i) {
            int idx = tid + i * 256;           // 0..2047
            int r = idx >> 3, c = idx & 7;
            const __half* src = (r < 128)
                ? g_Tb_h + (size_t)(row0 + r) * NN + k + c * 8
                : g_Xh   + (size_t)(col0 + r - 128) * NN + k + c * 8;
            cp16(base + r * ROWB + c * 16, src);
        }
        CP_COMMIT();
    };

    float acc[4][4][4] = {};
    issue(0, 0); issue(1, 1);

    for (int s = 0; s < 16; ++s) {
        CP_WAIT(1);
        __syncthreads();
        const uint32_t sA = sbase + (s % 3) * F_STG;
        const uint32_t sB = sA + 128 * ROWB;

        uint32_t a[4][4], b[2][4];
        LDS_Am(a, 4, 0, sA); LDS_B(b, 0, sB);
        if (s + 2 < 16) issue(s + 2, (s + 2) % 3); else CP_COMMIT();
        MMA_Mx4(acc, a, b, 4);
        #pragma unroll
        for (int k16 = 1; k16 < 4; ++k16) {
            LDS_Am(a, 4, k16, sA); LDS_B(b, k16, sB);
            MMA_Mx4(acc, a, b, 4);
        }
    }

    const int g  = lane >> 2;
    const int i2 = (lane & 3) * 2;
    #pragma unroll
    for (int mt = 0; mt < 4; ++mt)
        #pragma unroll
        for (int nt = 0; nt < 4; ++nt) {
            const int m0    = row0 + wm + mt * 16 + g;
            const int ncolg = col0 + wn + nt * 8 + i2;
            const int batch = ncolg >> 6;
            const int d     = ncolg & 63;
            float* o0 = outp + ((size_t)batch * NN + m0) * BD + d;
            float* o1 = outp + ((size_t)batch * NN + m0 + 8) * BD + d;
            *(float2*)o0 = make_float2(acc[mt][nt][0], acc[mt][nt][1]);
            *(float2*)o1 = make_float2(acc[mt][nt][2], acc[mt][nt][3]);
        }
}

// ============================================================================
// Host orchestration (single-fp16 pipeline, fused step epilogue):
//   T = fp16(W7); for k = 6..0: T = fp16(T @ S + Wk);  out = T @ fp16(X)
// ============================================================================
extern "C" void kernel_launch(void* const* d_in, const int* in_sizes, int n_in,
                              void* d_out, int out_size) {
    const float* nodes  = (const float*)d_in[0];   // [128, 1024, 64]
    const float* weight = (const float*)d_in[1];   // [8, 1024, 1024]
    const float* S      = (const float*)d_in[2];   // [1024, 1024]
    float* out = (float*)d_out;                    // [128, 1024, 64]

    cudaFuncSetAttribute(gemm_step,  cudaFuncAttributeMaxDynamicSharedMemorySize, ST_SMEM);
    cudaFuncSetAttribute(gemm_final, cudaFuncAttributeMaxDynamicSharedMemorySize, F_SMEM);

    convert_St  <<<dim3(16, 16), 256>>>(S);
    convert_X   <<<dim3(16, NB), 256>>>(nodes);
    convert_init<<<NN2 / 512, 256>>>(weight + (size_t)7 * NN2);

    for (int step = 0; step < 7; ++step) {
        int inSel = step & 1;  // 0: read Ta (write Tb), 1: read Tb (write Ta)
        gemm_step<<<dim3(16, 16), 128, ST_SMEM>>>(
            inSel, weight + (size_t)(6 - step) * NN2);
    }
    // 7 steps: final operator lands in Tb
    gemm_final<<<dim3(64, 8), 256, F_SMEM>>>(out);
}